// round 15
// baseline (speedup 1.0000x reference)
#include <cuda_runtime.h>
#include <math.h>

#define KP 16384
#define DP 2048
#define DECAYF 0.99f
#define THRESHF 0.5f

// __device__ scratch (no allocations allowed)
__device__ float g_dot[KP];     // z . p_i (original row indexing; cold path)
__device__ float g_pn2[KP];     // ||p_i||^2 (cold path)
__device__ float g_logit[KP];   // temp * cos(z, p_i)  (original row indexing)
__device__ float g_exp[KP];     // exp(g_logit)
__device__ float g_a[KP];       // EMA coef of z (cold path)
__device__ float g_b[KP];       // EMA coef of p (cold path)
// packed argmin: (usage_bits << 32) | idx ; reset at end of k2 each launch
__device__ unsigned long long g_min_packed = 0xFFFFFFFFFFFFFFFFULL;
__device__ int g_done = 0;      // argmin-partials completion counter

// ---------------- block reduction helpers (1024-thr kernel) ----------------
__device__ __forceinline__ float block_sum(float v, float* red) {
    int lane = threadIdx.x & 31, w = threadIdx.x >> 5;
    #pragma unroll
    for (int o = 16; o; o >>= 1) v += __shfl_down_sync(0xffffffffu, v, o);
    if (lane == 0) red[w] = v;
    __syncthreads();
    if (w == 0) {
        v = red[lane];
        #pragma unroll
        for (int o = 16; o; o >>= 1) v += __shfl_down_sync(0xffffffffu, v, o);
        if (lane == 0) red[0] = v;
    }
    __syncthreads();
    float r = red[0];
    __syncthreads();
    return r;
}

__device__ __forceinline__ float block_max(float v, float* red) {
    int lane = threadIdx.x & 31, w = threadIdx.x >> 5;
    #pragma unroll
    for (int o = 16; o; o >>= 1) v = fmaxf(v, __shfl_down_sync(0xffffffffu, v, o));
    if (lane == 0) red[w] = v;
    __syncthreads();
    if (w == 0) {
        v = red[lane];
        #pragma unroll
        for (int o = 16; o; o >>= 1) v = fmaxf(v, __shfl_down_sync(0xffffffffu, v, o));
        if (lane == 0) red[0] = v;
    }
    __syncthreads();
    float r = red[0];
    __syncthreads();
    return r;
}

__device__ __forceinline__ void block_argmax(float v, int idx, float* red, int* redi,
                                             float* ov, int* oi) {
    int lane = threadIdx.x & 31, w = threadIdx.x >> 5;
    #pragma unroll
    for (int o = 16; o; o >>= 1) {
        float v2 = __shfl_down_sync(0xffffffffu, v, o);
        int   i2 = __shfl_down_sync(0xffffffffu, idx, o);
        if (v2 > v || (v2 == v && i2 < idx)) { v = v2; idx = i2; }
    }
    if (lane == 0) { red[w] = v; redi[w] = idx; }
    __syncthreads();
    if (w == 0) {
        v = red[lane]; idx = redi[lane];
        #pragma unroll
        for (int o = 16; o; o >>= 1) {
            float v2 = __shfl_down_sync(0xffffffffu, v, o);
            int   i2 = __shfl_down_sync(0xffffffffu, idx, o);
            if (v2 > v || (v2 == v && i2 < idx)) { v = v2; idx = i2; }
        }
        if (lane == 0) { red[0] = v; redi[0] = idx; }
    }
    __syncthreads();
    *ov = red[0]; *oi = redi[0];
    __syncthreads();
}

// ---------------- fused kernel: argmin + row copy/dot/logit/exp, MLP=16 ----------
// Blocks 0-15: packed-argmin partials of usages -> g_min_packed, bump g_done.
// All blocks stage z, spin for g_done==16, broadcast bidx, compute znorm2 from
// smem. Row blocks copy source row to out (aligned-shift stores) and emit
// g_dot/g_pn2/g_logit/g_exp at the SOURCE index; block 4096 does the same for
// the evicted row only. exp work is spread over all SMs (was k2's bottleneck).
__global__ void __launch_bounds__(128, 4)
k1_fused(const float* __restrict__ z,
         const float* __restrict__ p,
         const float* __restrict__ usages,
         const float* __restrict__ temp,
         float* __restrict__ out) {
    __shared__ float4 zs[DP / 4];            // 8 KB staged z
    __shared__ int s_bidx;
    __shared__ float s_zn[4];
    const int warp = threadIdx.x >> 5, lane = threadIdx.x & 31;
    const float tempv = temp[0];

    // stage z (bidx-independent)
    #pragma unroll
    for (int i = threadIdx.x; i < DP / 4; i += 128)
        zs[i] = ((const float4*)z)[i];

    // argmin partials: blocks 0-15, 8 elems/thread via two float4 loads
    if (blockIdx.x < 16) {
        __shared__ unsigned long long redp[4];
        const int base = blockIdx.x * 1024 + threadIdx.x * 8;
        unsigned long long pk = 0xFFFFFFFFFFFFFFFFULL;
        #pragma unroll
        for (int q = 0; q < 2; ++q) {
            float4 uv = ((const float4*)(usages + base))[q];
            float u4[4] = {uv.x, uv.y, uv.z, uv.w};
            #pragma unroll
            for (int r = 0; r < 4; ++r) {
                unsigned long long c =
                    ((unsigned long long)__float_as_uint(u4[r]) << 32)
                    | (unsigned)(base + q * 4 + r);
                if (c < pk) pk = c;
            }
        }
        #pragma unroll
        for (int o = 16; o; o >>= 1) {
            unsigned long long p2 = __shfl_down_sync(0xffffffffu, pk, o);
            if (p2 < pk) pk = p2;
        }
        if (lane == 0) redp[warp] = pk;
        __syncthreads();
        if (threadIdx.x == 0) {
            unsigned long long m = redp[0];
            if (redp[1] < m) m = redp[1];
            if (redp[2] < m) m = redp[2];
            if (redp[3] < m) m = redp[3];
            atomicMin(&g_min_packed, m);
            __threadfence();
            atomicAdd(&g_done, 1);
        }
    }

    // spin until argmin complete, then broadcast bidx
    if (threadIdx.x == 0) {
        while (*((volatile int*)&g_done) < 16) { __nanosleep(64); }
        unsigned long long pk = atomicAdd(&g_min_packed, 0ULL);
        s_bidx = (int)(pk & 0xFFFFFFFFu);
    }
    __syncthreads();  // bidx broadcast + zs visible
    const int bidx = s_bidx;

    // znorm2 from staged z: each warp reduces its quarter (4 float4/lane)
    {
        float zn = 0.f;
        #pragma unroll
        for (int k = 0; k < 4; ++k) {
            float4 zc = zs[warp * 128 + lane + 32 * k];
            zn += zc.x * zc.x + zc.y * zc.y + zc.z * zc.z + zc.w * zc.w;
        }
        #pragma unroll
        for (int o = 16; o; o >>= 1)
            zn += __shfl_down_sync(0xffffffffu, zn, o);
        if (lane == 0) s_zn[warp] = zn;
    }
    __syncthreads();
    const float rz = rsqrtf(s_zn[0] + s_zn[1] + s_zn[2] + s_zn[3]);

    if (blockIdx.x == 4096) {  // evicted row only (4 warps, quarter each)
        __shared__ float s_d[4], s_n[4];
        const float4* src = (const float4*)(p + (size_t)bidx * DP) + warp * 128;
        float dot = 0.f, n2 = 0.f;
        #pragma unroll
        for (int k = 0; k < 4; ++k) {
            float4 v = src[lane + 32 * k];
            float4 zc = zs[warp * 128 + lane + 32 * k];
            dot += v.x * zc.x + v.y * zc.y + v.z * zc.z + v.w * zc.w;
            n2  += v.x * v.x + v.y * v.y + v.z * v.z + v.w * v.w;
        }
        #pragma unroll
        for (int o = 16; o; o >>= 1) {
            dot += __shfl_down_sync(0xffffffffu, dot, o);
            n2  += __shfl_down_sync(0xffffffffu, n2, o);
        }
        if (lane == 0) { s_d[warp] = dot; s_n[warp] = n2; }
        __syncthreads();
        if (threadIdx.x == 0) {
            float dot4 = s_d[0] + s_d[1] + s_d[2] + s_d[3];
            float n24  = s_n[0] + s_n[1] + s_n[2] + s_n[3];
            g_dot[bidx] = dot4; g_pn2[bidx] = n24;
            float l = tempv * dot4 * rz * rsqrtf(n24);
            g_logit[bidx] = l;
            g_exp[bidx] = expf(l);
        }
        return;
    }

    const int rowOut = blockIdx.x * 4 + warp;
    const bool is_z = (rowOut == KP - 1);
    const int s = (rowOut < bidx) ? rowOut : rowOut + 1;

    const float4* src = is_z ? (const float4*)zs
                             : (const float4*)(p + (size_t)s * DP);

    float4 v[16];
    #pragma unroll
    for (int k = 0; k < 16; ++k) v[k] = src[lane + 32 * k];

    if (!is_z) {
        float dot = 0.f, n2 = 0.f;
        #pragma unroll
        for (int k = 0; k < 16; ++k) {
            float4 zc = zs[lane + 32 * k];
            dot += v[k].x * zc.x + v[k].y * zc.y + v[k].z * zc.z + v[k].w * zc.w;
            n2  += v[k].x * v[k].x + v[k].y * v[k].y + v[k].z * v[k].z + v[k].w * v[k].w;
        }
        #pragma unroll
        for (int o = 16; o; o >>= 1) {
            dot += __shfl_down_sync(0xffffffffu, dot, o);
            n2  += __shfl_down_sync(0xffffffffu, n2, o);
        }
        if (lane == 0) {
            g_dot[s] = dot; g_pn2[s] = n2;
            float l = tempv * dot * rz * rsqrtf(n2);
            g_logit[s] = l;
            g_exp[s] = expf(l);
        }
    }

    float sh[16];
    #pragma unroll
    for (int k = 0; k < 16; ++k)
        sh[k] = __shfl_sync(0xffffffffu, v[k].x, (lane + 1) & 31);

    float* orow = out + 3 + (size_t)rowOut * DP;
    #pragma unroll
    for (int k = 0; k < 16; ++k) {
        int c = lane + 32 * k;
        if (k == 15 && lane == 31) {
            orow[2045] = v[k].y;
            orow[2046] = v[k].z;
            orow[2047] = v[k].w;
        } else {
            float nx = (lane < 31) ? sh[k] : sh[k + 1];
            float4 wv;
            wv.x = v[k].y; wv.y = v[k].z; wv.z = v[k].w; wv.w = nx;
            *(float4*)(orow + 1 + 4 * c) = wv;
        }
    }
    if (lane == 0) orow[0] = v[0].x;
}

// ---------------- kernel 2: reductions only (no exp loops on hot path) --------------
__global__ void __launch_bounds__(1024, 1)
k2_scalars(const float* __restrict__ z,
           const float* __restrict__ usages,
           const float* __restrict__ beta,
           const float* __restrict__ gamma,
           const float* __restrict__ temp,
           const float* __restrict__ p,
           float* __restrict__ out) {
    __shared__ float red[32];
    __shared__ int redi[32];
    __shared__ float s_bU[1025];
    const int tid = threadIdx.x;
    const float tempv = temp[0];
    const int base = tid * 16;
    float* out_us = out + 3 + (size_t)KP * DP;

    float acc;
    {
        float v0 = z[tid], v1 = z[tid + 1024];
        acc = v0 * v0 + v1 * v1;
    }
    float znorm2 = block_sum(acc, red);
    float rz = rsqrtf(znorm2);

    // load logits / usages (register-resident, original indexing)
    float L[16], U[16];
    float mx = -INFINITY;
    #pragma unroll
    for (int q = 0; q < 4; ++q) {
        float4 lv = ((const float4*)g_logit)[tid * 4 + q];
        L[q * 4 + 0] = lv.x; L[q * 4 + 1] = lv.y;
        L[q * 4 + 2] = lv.z; L[q * 4 + 3] = lv.w;
        float4 uv = ((const float4*)usages)[tid * 4 + q];
        U[q * 4 + 0] = uv.x; U[q * 4 + 1] = uv.y;
        U[q * 4 + 2] = uv.z; U[q * 4 + 3] = uv.w;
    }
    #pragma unroll
    for (int j = 0; j < 16; ++j) mx = fmaxf(mx, L[j]);
    float maxl = block_max(mx, red);

    float x = (-maxl - beta[0]) / gamma[0];
    float u = 1.f / (1.f + expf(-x));
    int evict = (u >= THRESHF) ? 1 : 0;

    if (evict) {
        const int bidx = (int)(g_min_packed & 0xFFFFFFFFu);
        const float l_z = tempv * znorm2 * rz * rz;  // appended z row's logit

        // new usages (shifted), boundary element via smem
        s_bU[tid] = U[0];
        __syncthreads();
        #pragma unroll
        for (int j = 0; j < 16; ++j) {
            int i = base + j;
            float nu;
            if (i == KP - 1)      nu = 1.0f;
            else if (i < bidx)    nu = U[j];
            else if (j < 15)      nu = U[j + 1];
            else                  nu = s_bU[tid + 1];
            out_us[i] = nu * DECAYF;
        }

        // argmax over logits2 (new-index space via monotonic remap + z row)
        float mv2 = l_z; int mi2 = KP - 1;
        #pragma unroll
        for (int j = 0; j < 16; ++j) {
            int i = base + j;
            if (i != bidx) {
                int ni = (i < bidx) ? i : i - 1;
                if (L[j] > mv2 || (L[j] == mv2 && ni < mi2)) { mv2 = L[j]; mi2 = ni; }
            }
        }
        float m2; int lab;
        block_argmax(mv2, mi2, red, redi, &m2, &lab);

        // S = sum of precomputed exp(logits) (fixed-order tree: deterministic)
        float se = 0.f;
        #pragma unroll
        for (int q = 0; q < 4; ++q) {
            float4 ev = ((const float4*)g_exp)[tid * 4 + q];
            se += ev.x + ev.y + ev.z + ev.w;
        }
        float S = block_sum(se, red);

        if (tid == 0) {
            float S2 = S - g_exp[bidx] + expf(l_z);
            out[0] = logf(S2) - m2;   // loss = log(sum exp(l2)) - max(l2)
            out[1] = (float)lab;
            out[2] = u;
        }
    } else {
        // ---------------- EMA branch (cold path; never taken by timed input) --------
        float se = 0.f;
        #pragma unroll
        for (int j = 0; j < 16; ++j) se += expf(L[j] - maxl);
        float sumexp = block_sum(se, red);

        float mv2 = -INFINITY; int mi2 = 0;
        float A[16], B[16];
        #pragma unroll
        for (int q = 0; q < 4; ++q) {
            float4 dv = ((const float4*)g_dot)[tid * 4 + q];
            float4 nv = ((const float4*)g_pn2)[tid * 4 + q];
            float dvv[4] = {dv.x, dv.y, dv.z, dv.w};
            float nvv[4] = {nv.x, nv.y, nv.z, nv.w};
            #pragma unroll
            for (int r = 0; r < 4; ++r) {
                int j = q * 4 + r;
                int i = base + j;
                float y = expf(L[j] - maxl) / sumexp;
                float delta = y * (1.f - u);
                float us = U[j];
                float a = delta / (delta + us);
                float bb = us / (us + delta);
                A[j] = a; B[j] = bb;
                out_us[i] = (us + delta) * DECAYF;
                float dotn = a * znorm2 + bb * dvv[r];
                float nn2 = a * a * znorm2 + 2.f * a * bb * dvv[r] + bb * bb * nvv[r];
                float l2 = tempv * dotn * rz * rsqrtf(nn2);
                L[j] = l2;
                if (l2 > mv2) { mv2 = l2; mi2 = i; }
            }
        }
        #pragma unroll
        for (int j = 0; j < 16; ++j) { g_a[base + j] = A[j]; g_b[base + j] = B[j]; }

        float m2; int lab;
        block_argmax(mv2, mi2, red, redi, &m2, &lab);

        float s2 = 0.f;
        #pragma unroll
        for (int j = 0; j < 16; ++j) s2 += expf(L[j] - m2);
        float sum2 = block_sum(s2, red);

        if (tid == 0) {
            out[0] = logf(sum2);
            out[1] = (float)lab;
            out[2] = u;
        }
        __syncthreads();

        // in-block EMA rewrite of all rows (slow, cold-path-only, correct)
        const float4* z4 = (const float4*)z;
        for (int row = 0; row < KP; ++row) {
            float a = g_a[row], bb = g_b[row];
            const float4* pr4 = (const float4*)(p + (size_t)row * DP);
            float* orow = out + 3 + (size_t)row * DP;
            __syncthreads();
            if (tid < 512) {
                float4 pv = pr4[tid], zv = z4[tid];
                s_bU[tid] = fmaf(a, zv.x, bb * pv.x);
            }
            __syncthreads();
            if (tid < 512) {
                float4 pv = pr4[tid], zv = z4[tid];
                float4 v;
                v.x = fmaf(a, zv.x, bb * pv.x);
                v.y = fmaf(a, zv.y, bb * pv.y);
                v.z = fmaf(a, zv.z, bb * pv.z);
                v.w = fmaf(a, zv.w, bb * pv.w);
                if (tid < 511) {
                    float4 wv;
                    wv.x = v.y; wv.y = v.z; wv.z = v.w; wv.w = s_bU[tid + 1];
                    *(float4*)(orow + 1 + 4 * tid) = wv;
                } else {
                    orow[2045] = v.y;
                    orow[2046] = v.z;
                    orow[2047] = v.w;
                    orow[0] = s_bU[0];
                }
            }
        }
    }

    // reset handoff state for the next launch (all consumers done)
    __syncthreads();
    if (tid == 0) {
        g_min_packed = 0xFFFFFFFFFFFFFFFFULL;
        g_done = 0;
    }
}

extern "C" void kernel_launch(void* const* d_in, const int* in_sizes, int n_in,
                              void* d_out, int out_size) {
    const float* z     = (const float*)d_in[0];
    const float* p     = (const float*)d_in[1];
    const float* us    = (const float*)d_in[2];
    const float* beta  = (const float*)d_in[3];
    const float* gamma = (const float*)d_in[4];
    const float* temp  = (const float*)d_in[5];
    float* out = (float*)d_out;

    k1_fused<<<4097, 128>>>(z, p, us, temp, out);
    k2_scalars<<<1, 1024>>>(z, us, beta, gamma, temp, p, out);
}

// round 16
// speedup vs baseline: 1.3233x; 1.3233x over previous
#include <cuda_runtime.h>
#include <math.h>

#define KP 16384
#define DP 2048
#define DECAYF 0.99f
#define THRESHF 0.5f

// __device__ scratch (no allocations allowed)
__device__ float g_dot[KP];     // z . p_i (original row indexing)
__device__ float g_pn2[KP];     // ||p_i||^2
__device__ float g_ndot[KP];    // dot * rsqrt(pn2)  (logit = temp * rz * ndot)
__device__ float g_a[KP];       // EMA coef of z (cold path)
__device__ float g_b[KP];       // EMA coef of p (cold path)
__device__ float g_partS[16];   // partial sums of exp(logit)
// packed argmin: (usage_bits << 32) | idx ; reset at end of k2 each launch
__device__ unsigned long long g_min_packed = 0xFFFFFFFFFFFFFFFFULL;
__device__ int g_done = 0;      // argmin-partials completion counter
__device__ int g_done2 = 0;     // exp-partials completion counter

// ---------------- block reduction helpers (1024-thr kernel) ----------------
__device__ __forceinline__ float block_sum(float v, float* red) {
    int lane = threadIdx.x & 31, w = threadIdx.x >> 5;
    #pragma unroll
    for (int o = 16; o; o >>= 1) v += __shfl_down_sync(0xffffffffu, v, o);
    if (lane == 0) red[w] = v;
    __syncthreads();
    if (w == 0) {
        v = red[lane];
        #pragma unroll
        for (int o = 16; o; o >>= 1) v += __shfl_down_sync(0xffffffffu, v, o);
        if (lane == 0) red[0] = v;
    }
    __syncthreads();
    float r = red[0];
    __syncthreads();
    return r;
}

__device__ __forceinline__ float block_max(float v, float* red) {
    int lane = threadIdx.x & 31, w = threadIdx.x >> 5;
    #pragma unroll
    for (int o = 16; o; o >>= 1) v = fmaxf(v, __shfl_down_sync(0xffffffffu, v, o));
    if (lane == 0) red[w] = v;
    __syncthreads();
    if (w == 0) {
        v = red[lane];
        #pragma unroll
        for (int o = 16; o; o >>= 1) v = fmaxf(v, __shfl_down_sync(0xffffffffu, v, o));
        if (lane == 0) red[0] = v;
    }
    __syncthreads();
    float r = red[0];
    __syncthreads();
    return r;
}

__device__ __forceinline__ void block_argmax(float v, int idx, float* red, int* redi,
                                             float* ov, int* oi) {
    int lane = threadIdx.x & 31, w = threadIdx.x >> 5;
    #pragma unroll
    for (int o = 16; o; o >>= 1) {
        float v2 = __shfl_down_sync(0xffffffffu, v, o);
        int   i2 = __shfl_down_sync(0xffffffffu, idx, o);
        if (v2 > v || (v2 == v && i2 < idx)) { v = v2; idx = i2; }
    }
    if (lane == 0) { red[w] = v; redi[w] = idx; }
    __syncthreads();
    if (w == 0) {
        v = red[lane]; idx = redi[lane];
        #pragma unroll
        for (int o = 16; o; o >>= 1) {
            float v2 = __shfl_down_sync(0xffffffffu, v, o);
            int   i2 = __shfl_down_sync(0xffffffffu, idx, o);
            if (v2 > v || (v2 == v && i2 < idx)) { v = v2; idx = i2; }
        }
        if (lane == 0) { red[0] = v; redi[0] = idx; }
    }
    __syncthreads();
    *ov = red[0]; *oi = redi[0];
    __syncthreads();
}

// ---------------- fused kernel: argmin (blocks 0-15) + row copy/dot, MLP=16 ----------
// R14-proven structure; only addition: lane 0 also stores g_ndot = dot*rsqrt(n2).
__global__ void __launch_bounds__(128, 4)
k1_fused(const float* __restrict__ z,
         const float* __restrict__ p,
         const float* __restrict__ usages,
         float* __restrict__ out) {
    __shared__ float4 zs[DP / 4];            // 8 KB staged z
    __shared__ int s_bidx;
    const int warp = threadIdx.x >> 5, lane = threadIdx.x & 31;

    // stage z (bidx-independent)
    #pragma unroll
    for (int i = threadIdx.x; i < DP / 4; i += 128)
        zs[i] = ((const float4*)z)[i];

    // argmin partials: blocks 0-15, 8 elems/thread via two float4 loads
    if (blockIdx.x < 16) {
        __shared__ unsigned long long redp[4];
        const int base = blockIdx.x * 1024 + threadIdx.x * 8;
        unsigned long long pk = 0xFFFFFFFFFFFFFFFFULL;
        #pragma unroll
        for (int q = 0; q < 2; ++q) {
            float4 uv = ((const float4*)(usages + base))[q];
            float u4[4] = {uv.x, uv.y, uv.z, uv.w};
            #pragma unroll
            for (int r = 0; r < 4; ++r) {
                unsigned long long c =
                    ((unsigned long long)__float_as_uint(u4[r]) << 32)
                    | (unsigned)(base + q * 4 + r);
                if (c < pk) pk = c;
            }
        }
        #pragma unroll
        for (int o = 16; o; o >>= 1) {
            unsigned long long p2 = __shfl_down_sync(0xffffffffu, pk, o);
            if (p2 < pk) pk = p2;
        }
        if (lane == 0) redp[warp] = pk;
        __syncthreads();
        if (threadIdx.x == 0) {
            unsigned long long m = redp[0];
            if (redp[1] < m) m = redp[1];
            if (redp[2] < m) m = redp[2];
            if (redp[3] < m) m = redp[3];
            atomicMin(&g_min_packed, m);
            __threadfence();
            atomicAdd(&g_done, 1);
        }
    }

    // spin until argmin complete, then broadcast bidx
    if (threadIdx.x == 0) {
        while (*((volatile int*)&g_done) < 16) { __nanosleep(64); }
        unsigned long long pk = atomicAdd(&g_min_packed, 0ULL);
        s_bidx = (int)(pk & 0xFFFFFFFFu);
    }
    __syncthreads();
    const int bidx = s_bidx;

    if (blockIdx.x == 4096) {  // evicted row's dot/norm (4 warps, quarter each)
        __shared__ float s_d[4], s_n[4];
        const float4* src = (const float4*)(p + (size_t)bidx * DP) + warp * 128;
        float dot = 0.f, n2 = 0.f;
        #pragma unroll
        for (int k = 0; k < 4; ++k) {
            float4 v = src[lane + 32 * k];
            float4 zc = zs[warp * 128 + lane + 32 * k];
            dot += v.x * zc.x + v.y * zc.y + v.z * zc.z + v.w * zc.w;
            n2  += v.x * v.x + v.y * v.y + v.z * v.z + v.w * v.w;
        }
        #pragma unroll
        for (int o = 16; o; o >>= 1) {
            dot += __shfl_down_sync(0xffffffffu, dot, o);
            n2  += __shfl_down_sync(0xffffffffu, n2, o);
        }
        if (lane == 0) { s_d[warp] = dot; s_n[warp] = n2; }
        __syncthreads();
        if (threadIdx.x == 0) {
            float dot4 = s_d[0] + s_d[1] + s_d[2] + s_d[3];
            float n24  = s_n[0] + s_n[1] + s_n[2] + s_n[3];
            g_dot[bidx] = dot4;
            g_pn2[bidx] = n24;
            g_ndot[bidx] = dot4 * rsqrtf(n24);
        }
        return;
    }

    const int rowOut = blockIdx.x * 4 + warp;
    const bool is_z = (rowOut == KP - 1);
    const int s = (rowOut < bidx) ? rowOut : rowOut + 1;

    const float4* src = is_z ? (const float4*)zs
                             : (const float4*)(p + (size_t)s * DP);

    float4 v[16];
    #pragma unroll
    for (int k = 0; k < 16; ++k) v[k] = src[lane + 32 * k];

    if (!is_z) {
        float dot = 0.f, n2 = 0.f;
        #pragma unroll
        for (int k = 0; k < 16; ++k) {
            float4 zc = zs[lane + 32 * k];
            dot += v[k].x * zc.x + v[k].y * zc.y + v[k].z * zc.z + v[k].w * zc.w;
            n2  += v[k].x * v[k].x + v[k].y * v[k].y + v[k].z * v[k].z + v[k].w * v[k].w;
        }
        #pragma unroll
        for (int o = 16; o; o >>= 1) {
            dot += __shfl_down_sync(0xffffffffu, dot, o);
            n2  += __shfl_down_sync(0xffffffffu, n2, o);
        }
        if (lane == 0) {
            g_dot[s] = dot;
            g_pn2[s] = n2;
            g_ndot[s] = dot * rsqrtf(n2);
        }
    }

    float sh[16];
    #pragma unroll
    for (int k = 0; k < 16; ++k)
        sh[k] = __shfl_sync(0xffffffffu, v[k].x, (lane + 1) & 31);

    float* orow = out + 3 + (size_t)rowOut * DP;
    #pragma unroll
    for (int k = 0; k < 16; ++k) {
        int c = lane + 32 * k;
        if (k == 15 && lane == 31) {
            orow[2045] = v[k].y;
            orow[2046] = v[k].z;
            orow[2047] = v[k].w;
        } else {
            float nx = (lane < 31) ? sh[k] : sh[k + 1];
            float4 wv;
            wv.x = v[k].y; wv.y = v[k].z; wv.z = v[k].w; wv.w = nx;
            *(float4*)(orow + 1 + 4 * c) = wv;
        }
    }
    if (lane == 0) orow[0] = v[0].x;
}

// ---------------- kernel 2: 17 blocks. Blocks 1-16: partial exp sums (MUFU
// spread over 16 SMs). Block 0: all scalar outputs; spins for partials only at
// the very end. Deterministic: g_partS summed in fixed order by one thread.
__global__ void __launch_bounds__(1024, 1)
k2_scalars(const float* __restrict__ z,
           const float* __restrict__ usages,
           const float* __restrict__ beta,
           const float* __restrict__ gamma,
           const float* __restrict__ temp,
           const float* __restrict__ p,
           float* __restrict__ out) {
    __shared__ float red[32];
    __shared__ int redi[32];
    __shared__ float s_bU[1025];
    const int tid = threadIdx.x;
    const float tempv = temp[0];

    // ||z||^2 (all 17 blocks; cheap, removes cross-block dependency)
    float acc;
    {
        float v0 = z[tid], v1 = z[tid + 1024];
        acc = v0 * v0 + v1 * v1;
    }
    float znorm2 = block_sum(acc, red);
    float rz = rsqrtf(znorm2);

    if (blockIdx.x != 0) {
        // partial sum of exp(logit) over rows [(b-1)*1024, b*1024)
        int i = (int)(blockIdx.x - 1) * 1024 + tid;
        float l = tempv * rz * g_ndot[i];
        float S = block_sum(expf(l), red);
        if (tid == 0) {
            g_partS[blockIdx.x - 1] = S;
            __threadfence();
            atomicAdd(&g_done2, 1);
        }
        return;
    }

    // -------- block 0: scalar phase --------
    const int base = tid * 16;
    float* out_us = out + 3 + (size_t)KP * DP;

    // logits from g_ndot (no per-element MUFU), usages
    float L[16], U[16];
    float mx = -INFINITY;
    #pragma unroll
    for (int q = 0; q < 4; ++q) {
        float4 nd = ((const float4*)g_ndot)[tid * 4 + q];
        L[q * 4 + 0] = tempv * rz * nd.x;
        L[q * 4 + 1] = tempv * rz * nd.y;
        L[q * 4 + 2] = tempv * rz * nd.z;
        L[q * 4 + 3] = tempv * rz * nd.w;
        float4 uv = ((const float4*)usages)[tid * 4 + q];
        U[q * 4 + 0] = uv.x; U[q * 4 + 1] = uv.y;
        U[q * 4 + 2] = uv.z; U[q * 4 + 3] = uv.w;
    }
    #pragma unroll
    for (int j = 0; j < 16; ++j) mx = fmaxf(mx, L[j]);
    float maxl = block_max(mx, red);

    float x = (-maxl - beta[0]) / gamma[0];
    float u = 1.f / (1.f + expf(-x));
    int evict = (u >= THRESHF) ? 1 : 0;

    if (evict) {
        const int bidx = (int)(g_min_packed & 0xFFFFFFFFu);
        const float l_z = tempv * znorm2 * rz * rz;  // appended z row's logit

        // new usages (shifted), boundary element via smem
        s_bU[tid] = U[0];
        __syncthreads();
        #pragma unroll
        for (int j = 0; j < 16; ++j) {
            int i = base + j;
            float nu;
            if (i == KP - 1)      nu = 1.0f;
            else if (i < bidx)    nu = U[j];
            else if (j < 15)      nu = U[j + 1];
            else                  nu = s_bU[tid + 1];
            out_us[i] = nu * DECAYF;
        }

        // argmax over logits2 (new-index space via monotonic remap + z row)
        float mv2 = l_z; int mi2 = KP - 1;
        #pragma unroll
        for (int j = 0; j < 16; ++j) {
            int i = base + j;
            if (i != bidx) {
                int ni = (i < bidx) ? i : i - 1;
                if (L[j] > mv2 || (L[j] == mv2 && ni < mi2)) { mv2 = L[j]; mi2 = ni; }
            }
        }
        float m2; int lab;
        block_argmax(mv2, mi2, red, redi, &m2, &lab);

        if (tid == 0) {
            // wait for the 16 partial exp sums, then combine in fixed order
            while (*((volatile int*)&g_done2) < 16) { __nanosleep(64); }
            __threadfence();
            float S = 0.f;
            #pragma unroll
            for (int k = 0; k < 16; ++k) S += g_partS[k];
            float l_b = tempv * rz * g_ndot[bidx];
            float S2 = S - expf(l_b) + expf(l_z);
            out[0] = logf(S2) - m2;   // loss = log(sum exp(l2)) - max(l2)
            out[1] = (float)lab;
            out[2] = u;
        }
    } else {
        // ---------------- EMA branch (cold path; never taken by timed input) --------
        float se = 0.f;
        #pragma unroll
        for (int j = 0; j < 16; ++j) se += expf(L[j] - maxl);
        float sumexp = block_sum(se, red);

        float mv2 = -INFINITY; int mi2 = 0;
        float A[16], B[16];
        #pragma unroll
        for (int q = 0; q < 4; ++q) {
            float4 dv = ((const float4*)g_dot)[tid * 4 + q];
            float4 nv = ((const float4*)g_pn2)[tid * 4 + q];
            float dvv[4] = {dv.x, dv.y, dv.z, dv.w};
            float nvv[4] = {nv.x, nv.y, nv.z, nv.w};
            #pragma unroll
            for (int r = 0; r < 4; ++r) {
                int j = q * 4 + r;
                int i = base + j;
                float y = expf(L[j] - maxl) / sumexp;
                float delta = y * (1.f - u);
                float us = U[j];
                float a = delta / (delta + us);
                float bb = us / (us + delta);
                A[j] = a; B[j] = bb;
                out_us[i] = (us + delta) * DECAYF;
                float dotn = a * znorm2 + bb * dvv[r];
                float nn2 = a * a * znorm2 + 2.f * a * bb * dvv[r] + bb * bb * nvv[r];
                float l2 = tempv * dotn * rz * rsqrtf(nn2);
                L[j] = l2;
                if (l2 > mv2) { mv2 = l2; mi2 = i; }
            }
        }
        #pragma unroll
        for (int j = 0; j < 16; ++j) { g_a[base + j] = A[j]; g_b[base + j] = B[j]; }

        float m2; int lab;
        block_argmax(mv2, mi2, red, redi, &m2, &lab);

        float s2 = 0.f;
        #pragma unroll
        for (int j = 0; j < 16; ++j) s2 += expf(L[j] - m2);
        float sum2 = block_sum(s2, red);

        if (tid == 0) {
            out[0] = logf(sum2);
            out[1] = (float)lab;
            out[2] = u;
        }
        __syncthreads();

        // in-block EMA rewrite of all rows (slow, cold-path-only, correct)
        const float4* z4 = (const float4*)z;
        for (int row = 0; row < KP; ++row) {
            float a = g_a[row], bb = g_b[row];
            const float4* pr4 = (const float4*)(p + (size_t)row * DP);
            float* orow = out + 3 + (size_t)row * DP;
            __syncthreads();
            if (tid < 512) {
                float4 pv = pr4[tid], zv = z4[tid];
                s_bU[tid] = fmaf(a, zv.x, bb * pv.x);
            }
            __syncthreads();
            if (tid < 512) {
                float4 pv = pr4[tid], zv = z4[tid];
                float4 v;
                v.x = fmaf(a, zv.x, bb * pv.x);
                v.y = fmaf(a, zv.y, bb * pv.y);
                v.z = fmaf(a, zv.z, bb * pv.z);
                v.w = fmaf(a, zv.w, bb * pv.w);
                if (tid < 511) {
                    float4 wv;
                    wv.x = v.y; wv.y = v.z; wv.z = v.w; wv.w = s_bU[tid + 1];
                    *(float4*)(orow + 1 + 4 * tid) = wv;
                } else {
                    orow[2045] = v.y;
                    orow[2046] = v.z;
                    orow[2047] = v.w;
                    orow[0] = s_bU[0];
                }
            }
        }
        // cold path must also drain the partial-sum counter before reset below
        if (tid == 0) {
            while (*((volatile int*)&g_done2) < 16) { __nanosleep(64); }
        }
    }

    // reset handoff state for the next launch (all consumers done)
    __syncthreads();
    if (tid == 0) {
        g_min_packed = 0xFFFFFFFFFFFFFFFFULL;
        g_done = 0;
        g_done2 = 0;
    }
}

extern "C" void kernel_launch(void* const* d_in, const int* in_sizes, int n_in,
                              void* d_out, int out_size) {
    const float* z     = (const float*)d_in[0];
    const float* p     = (const float*)d_in[1];
    const float* us    = (const float*)d_in[2];
    const float* beta  = (const float*)d_in[3];
    const float* gamma = (const float*)d_in[4];
    const float* temp  = (const float*)d_in[5];
    float* out = (float*)d_out;

    k1_fused<<<4097, 128>>>(z, p, us, out);
    k2_scalars<<<17, 1024>>>(z, us, beta, gamma, temp, p, out);
}

// round 17
// speedup vs baseline: 1.4451x; 1.0920x over previous
#include <cuda_runtime.h>
#include <math.h>

#define KP 16384
#define DP 2048
#define DECAYF 0.99f
#define THRESHF 0.5f

// __device__ scratch (no allocations allowed)
__device__ float g_dot[KP];     // z . p_i (original row indexing)
__device__ float g_pn2[KP];     // ||p_i||^2
__device__ float g_ndot[KP];    // dot * rsqrt(pn2)  (logit = temp * rz * ndot)
__device__ float g_a[KP];       // EMA coef of z (cold path)
__device__ float g_b[KP];       // EMA coef of p (cold path)
__device__ float g_partS[16];   // partial sums of exp(logit)
// packed argmin: (usage_bits << 32) | idx ; reset at end of k2 each launch
__device__ unsigned long long g_min_packed = 0xFFFFFFFFFFFFFFFFULL;
__device__ int g_done = 0;      // argmin-partials completion counter
__device__ int g_done2 = 0;     // exp-partials completion counter

// ---------------- block reduction helpers (1024-thr kernel) ----------------
__device__ __forceinline__ float block_sum(float v, float* red) {
    int lane = threadIdx.x & 31, w = threadIdx.x >> 5;
    #pragma unroll
    for (int o = 16; o; o >>= 1) v += __shfl_down_sync(0xffffffffu, v, o);
    if (lane == 0) red[w] = v;
    __syncthreads();
    if (w == 0) {
        v = red[lane];
        #pragma unroll
        for (int o = 16; o; o >>= 1) v += __shfl_down_sync(0xffffffffu, v, o);
        if (lane == 0) red[0] = v;
    }
    __syncthreads();
    float r = red[0];
    __syncthreads();
    return r;
}

__device__ __forceinline__ float block_max(float v, float* red) {
    int lane = threadIdx.x & 31, w = threadIdx.x >> 5;
    #pragma unroll
    for (int o = 16; o; o >>= 1) v = fmaxf(v, __shfl_down_sync(0xffffffffu, v, o));
    if (lane == 0) red[w] = v;
    __syncthreads();
    if (w == 0) {
        v = red[lane];
        #pragma unroll
        for (int o = 16; o; o >>= 1) v = fmaxf(v, __shfl_down_sync(0xffffffffu, v, o));
        if (lane == 0) red[0] = v;
    }
    __syncthreads();
    float r = red[0];
    __syncthreads();
    return r;
}

__device__ __forceinline__ void block_argmax(float v, int idx, float* red, int* redi,
                                             float* ov, int* oi) {
    int lane = threadIdx.x & 31, w = threadIdx.x >> 5;
    #pragma unroll
    for (int o = 16; o; o >>= 1) {
        float v2 = __shfl_down_sync(0xffffffffu, v, o);
        int   i2 = __shfl_down_sync(0xffffffffu, idx, o);
        if (v2 > v || (v2 == v && i2 < idx)) { v = v2; idx = i2; }
    }
    if (lane == 0) { red[w] = v; redi[w] = idx; }
    __syncthreads();
    if (w == 0) {
        v = red[lane]; idx = redi[lane];
        #pragma unroll
        for (int o = 16; o; o >>= 1) {
            float v2 = __shfl_down_sync(0xffffffffu, v, o);
            int   i2 = __shfl_down_sync(0xffffffffu, idx, o);
            if (v2 > v || (v2 == v && i2 < idx)) { v = v2; idx = i2; }
        }
        if (lane == 0) { red[0] = v; redi[0] = idx; }
    }
    __syncthreads();
    *ov = red[0]; *oi = redi[0];
    __syncthreads();
}

// ---------------- fused kernel: argmin (blocks 0-15) + row copy/dot, MLP=16 ----------
// R16-proven; unchanged.
__global__ void __launch_bounds__(128, 4)
k1_fused(const float* __restrict__ z,
         const float* __restrict__ p,
         const float* __restrict__ usages,
         float* __restrict__ out) {
    __shared__ float4 zs[DP / 4];            // 8 KB staged z
    __shared__ int s_bidx;
    const int warp = threadIdx.x >> 5, lane = threadIdx.x & 31;

    #pragma unroll
    for (int i = threadIdx.x; i < DP / 4; i += 128)
        zs[i] = ((const float4*)z)[i];

    if (blockIdx.x < 16) {
        __shared__ unsigned long long redp[4];
        const int base = blockIdx.x * 1024 + threadIdx.x * 8;
        unsigned long long pk = 0xFFFFFFFFFFFFFFFFULL;
        #pragma unroll
        for (int q = 0; q < 2; ++q) {
            float4 uv = ((const float4*)(usages + base))[q];
            float u4[4] = {uv.x, uv.y, uv.z, uv.w};
            #pragma unroll
            for (int r = 0; r < 4; ++r) {
                unsigned long long c =
                    ((unsigned long long)__float_as_uint(u4[r]) << 32)
                    | (unsigned)(base + q * 4 + r);
                if (c < pk) pk = c;
            }
        }
        #pragma unroll
        for (int o = 16; o; o >>= 1) {
            unsigned long long p2 = __shfl_down_sync(0xffffffffu, pk, o);
            if (p2 < pk) pk = p2;
        }
        if (lane == 0) redp[warp] = pk;
        __syncthreads();
        if (threadIdx.x == 0) {
            unsigned long long m = redp[0];
            if (redp[1] < m) m = redp[1];
            if (redp[2] < m) m = redp[2];
            if (redp[3] < m) m = redp[3];
            atomicMin(&g_min_packed, m);
            __threadfence();
            atomicAdd(&g_done, 1);
        }
    }

    if (threadIdx.x == 0) {
        while (*((volatile int*)&g_done) < 16) { __nanosleep(64); }
        unsigned long long pk = atomicAdd(&g_min_packed, 0ULL);
        s_bidx = (int)(pk & 0xFFFFFFFFu);
    }
    __syncthreads();
    const int bidx = s_bidx;

    if (blockIdx.x == 4096) {  // evicted row's dot/norm (4 warps, quarter each)
        __shared__ float s_d[4], s_n[4];
        const float4* src = (const float4*)(p + (size_t)bidx * DP) + warp * 128;
        float dot = 0.f, n2 = 0.f;
        #pragma unroll
        for (int k = 0; k < 4; ++k) {
            float4 v = src[lane + 32 * k];
            float4 zc = zs[warp * 128 + lane + 32 * k];
            dot += v.x * zc.x + v.y * zc.y + v.z * zc.z + v.w * zc.w;
            n2  += v.x * v.x + v.y * v.y + v.z * v.z + v.w * v.w;
        }
        #pragma unroll
        for (int o = 16; o; o >>= 1) {
            dot += __shfl_down_sync(0xffffffffu, dot, o);
            n2  += __shfl_down_sync(0xffffffffu, n2, o);
        }
        if (lane == 0) { s_d[warp] = dot; s_n[warp] = n2; }
        __syncthreads();
        if (threadIdx.x == 0) {
            float dot4 = s_d[0] + s_d[1] + s_d[2] + s_d[3];
            float n24  = s_n[0] + s_n[1] + s_n[2] + s_n[3];
            g_dot[bidx] = dot4;
            g_pn2[bidx] = n24;
            g_ndot[bidx] = dot4 * rsqrtf(n24);
        }
        return;
    }

    const int rowOut = blockIdx.x * 4 + warp;
    const bool is_z = (rowOut == KP - 1);
    const int s = (rowOut < bidx) ? rowOut : rowOut + 1;

    const float4* src = is_z ? (const float4*)zs
                             : (const float4*)(p + (size_t)s * DP);

    float4 v[16];
    #pragma unroll
    for (int k = 0; k < 16; ++k) v[k] = src[lane + 32 * k];

    if (!is_z) {
        float dot = 0.f, n2 = 0.f;
        #pragma unroll
        for (int k = 0; k < 16; ++k) {
            float4 zc = zs[lane + 32 * k];
            dot += v[k].x * zc.x + v[k].y * zc.y + v[k].z * zc.z + v[k].w * zc.w;
            n2  += v[k].x * v[k].x + v[k].y * v[k].y + v[k].z * v[k].z + v[k].w * v[k].w;
        }
        #pragma unroll
        for (int o = 16; o; o >>= 1) {
            dot += __shfl_down_sync(0xffffffffu, dot, o);
            n2  += __shfl_down_sync(0xffffffffu, n2, o);
        }
        if (lane == 0) {
            g_dot[s] = dot;
            g_pn2[s] = n2;
            g_ndot[s] = dot * rsqrtf(n2);
        }
    }

    float sh[16];
    #pragma unroll
    for (int k = 0; k < 16; ++k)
        sh[k] = __shfl_sync(0xffffffffu, v[k].x, (lane + 1) & 31);

    float* orow = out + 3 + (size_t)rowOut * DP;
    #pragma unroll
    for (int k = 0; k < 16; ++k) {
        int c = lane + 32 * k;
        if (k == 15 && lane == 31) {
            orow[2045] = v[k].y;
            orow[2046] = v[k].z;
            orow[2047] = v[k].w;
        } else {
            float nx = (lane < 31) ? sh[k] : sh[k + 1];
            float4 wv;
            wv.x = v[k].y; wv.y = v[k].z; wv.z = v[k].w; wv.w = nx;
            *(float4*)(orow + 1 + 4 * c) = wv;
        }
    }
    if (lane == 0) orow[0] = v[0].x;
}

// ---------------- kernel 2: 17 blocks, STRIDED ownership (all coalesced) ----------
// Blocks 1-16: partial exp sums. Block 0: scalar outputs via strided loops —
// thread handles {tid, 1024+tid, ...}; every LDG/STG is warp-coalesced.
__global__ void __launch_bounds__(1024, 1)
k2_scalars(const float* __restrict__ z,
           const float* __restrict__ usages,
           const float* __restrict__ beta,
           const float* __restrict__ gamma,
           const float* __restrict__ temp,
           const float* __restrict__ p,
           float* __restrict__ out) {
    __shared__ float red[32];
    __shared__ int redi[32];
    __shared__ float s_bU[1025];
    const int tid = threadIdx.x;
    const float tempv = temp[0];

    // ||z||^2 (all 17 blocks; removes cross-block dependency)
    float acc;
    {
        float v0 = z[tid], v1 = z[tid + 1024];
        acc = v0 * v0 + v1 * v1;
    }
    float znorm2 = block_sum(acc, red);
    float rz = rsqrtf(znorm2);

    if (blockIdx.x != 0) {
        int i = (int)(blockIdx.x - 1) * 1024 + tid;
        float l = tempv * rz * g_ndot[i];
        float S = block_sum(expf(l), red);
        if (tid == 0) {
            g_partS[blockIdx.x - 1] = S;
            __threadfence();
            atomicAdd(&g_done2, 1);
        }
        return;
    }

    // -------- block 0: scalar phase (strided, coalesced) --------
    float* out_us = out + 3 + (size_t)KP * DP;
    const float trz = tempv * rz;

    // max of original logits (coalesced loads)
    float mx = -INFINITY;
    #pragma unroll
    for (int k = 0; k < 16; ++k)
        mx = fmaxf(mx, trz * g_ndot[k * 1024 + tid]);
    float maxl = block_max(mx, red);

    float x = (-maxl - beta[0]) / gamma[0];
    float u = 1.f / (1.f + expf(-x));
    int evict = (u >= THRESHF) ? 1 : 0;

    if (evict) {
        const int bidx = (int)(g_min_packed & 0xFFFFFFFFu);
        const float l_z = tempv * znorm2 * rz * rz;  // appended z row's logit

        // per-output-row: shifted usage write + logits2 argmax (all coalesced)
        float mv2 = -INFINITY; int mi2 = 0;
        #pragma unroll
        for (int k = 0; k < 16; ++k) {
            int i = k * 1024 + tid;
            float nu, l2;
            if (i == KP - 1) {
                nu = 1.0f;
                l2 = l_z;
            } else {
                int src = (i < bidx) ? i : i + 1;
                nu = usages[src];
                l2 = trz * g_ndot[src];
            }
            out_us[i] = nu * DECAYF;
            if (l2 > mv2) { mv2 = l2; mi2 = i; }  // ascending i -> first occurrence
        }
        float m2; int lab;
        block_argmax(mv2, mi2, red, redi, &m2, &lab);

        if (tid == 0) {
            while (*((volatile int*)&g_done2) < 16) { __nanosleep(64); }
            __threadfence();
            float S = 0.f;
            #pragma unroll
            for (int k = 0; k < 16; ++k) S += g_partS[k];
            float l_b = trz * g_ndot[bidx];
            float S2 = S - expf(l_b) + expf(l_z);
            out[0] = logf(S2) - m2;   // loss = log(sum exp(l2)) - max(l2)
            out[1] = (float)lab;
            out[2] = u;
        }
    } else {
        // ---------------- EMA branch (cold path; never taken by timed input) --------
        float se = 0.f;
        #pragma unroll
        for (int k = 0; k < 16; ++k) {
            float l = trz * g_ndot[k * 1024 + tid];
            se += expf(l - maxl);
        }
        float sumexp = block_sum(se, red);

        float mv2 = -INFINITY; int mi2 = 0;
        #pragma unroll
        for (int k = 0; k < 16; ++k) {
            int i = k * 1024 + tid;
            float dv = g_dot[i];
            float nv = g_pn2[i];
            float l = trz * g_ndot[i];
            float y = expf(l - maxl) / sumexp;
            float delta = y * (1.f - u);
            float us = usages[i];
            float a = delta / (delta + us);
            float bb = us / (us + delta);
            g_a[i] = a; g_b[i] = bb;
            out_us[i] = (us + delta) * DECAYF;
            float dotn = a * znorm2 + bb * dv;
            float nn2 = a * a * znorm2 + 2.f * a * bb * dv + bb * bb * nv;
            float l2 = tempv * dotn * rz * rsqrtf(nn2);
            if (l2 > mv2) { mv2 = l2; mi2 = i; }
        }

        float m2; int lab;
        block_argmax(mv2, mi2, red, redi, &m2, &lab);

        float s2 = 0.f;
        #pragma unroll
        for (int k = 0; k < 16; ++k) {
            int i = k * 1024 + tid;
            float dv = g_dot[i];
            float nv = g_pn2[i];
            float a = g_a[i], bb = g_b[i];
            float dotn = a * znorm2 + bb * dv;
            float nn2 = a * a * znorm2 + 2.f * a * bb * dv + bb * bb * nv;
            float l2 = tempv * dotn * rz * rsqrtf(nn2);
            s2 += expf(l2 - m2);
        }
        float sum2 = block_sum(s2, red);

        if (tid == 0) {
            out[0] = logf(sum2);
            out[1] = (float)lab;
            out[2] = u;
        }
        __syncthreads();

        // in-block EMA rewrite of all rows (slow, cold-path-only, correct)
        const float4* z4 = (const float4*)z;
        for (int row = 0; row < KP; ++row) {
            float a = g_a[row], bb = g_b[row];
            const float4* pr4 = (const float4*)(p + (size_t)row * DP);
            float* orow = out + 3 + (size_t)row * DP;
            __syncthreads();
            if (tid < 512) {
                float4 pv = pr4[tid], zv = z4[tid];
                s_bU[tid] = fmaf(a, zv.x, bb * pv.x);
            }
            __syncthreads();
            if (tid < 512) {
                float4 pv = pr4[tid], zv = z4[tid];
                float4 v;
                v.x = fmaf(a, zv.x, bb * pv.x);
                v.y = fmaf(a, zv.y, bb * pv.y);
                v.z = fmaf(a, zv.z, bb * pv.z);
                v.w = fmaf(a, zv.w, bb * pv.w);
                if (tid < 511) {
                    float4 wv;
                    wv.x = v.y; wv.y = v.z; wv.z = v.w; wv.w = s_bU[tid + 1];
                    *(float4*)(orow + 1 + 4 * tid) = wv;
                } else {
                    orow[2045] = v.y;
                    orow[2046] = v.z;
                    orow[2047] = v.w;
                    orow[0] = s_bU[0];
                }
            }
        }
        if (tid == 0) {
            while (*((volatile int*)&g_done2) < 16) { __nanosleep(64); }
        }
    }

    // reset handoff state for the next launch (all consumers done)
    __syncthreads();
    if (tid == 0) {
        g_min_packed = 0xFFFFFFFFFFFFFFFFULL;
        g_done = 0;
        g_done2 = 0;
    }
}

extern "C" void kernel_launch(void* const* d_in, const int* in_sizes, int n_in,
                              void* d_out, int out_size) {
    const float* z     = (const float*)d_in[0];
    const float* p     = (const float*)d_in[1];
    const float* us    = (const float*)d_in[2];
    const float* beta  = (const float*)d_in[3];
    const float* gamma = (const float*)d_in[4];
    const float* temp  = (const float*)d_in[5];
    float* out = (float*)d_out;

    k1_fused<<<4097, 128>>>(z, p, us, out);
    k2_scalars<<<17, 1024>>>(z, us, beta, gamma, temp, p, out);
}